// round 4
// baseline (speedup 1.0000x reference)
#include <cuda_runtime.h>
#include <cuda_bf16.h>
#include <cstdint>

// Performer (FAVOR+) attention, fully fused: dash matrices never hit DRAM.
// All GEMMs via mma.sync bf16 split hi/lo (3-MMA). B=64,N=2048,d=64,m=266(->288).

#define B_      64
#define N_      2048
#define D_      64
#define M_      266
#define MP_     288
#define NROWS_  (B_ * N_)
#define SCALE_  0.35355339059327373f
#define NORMC_  0.0625f
#define RATIO_  0.06131393394849658f
#define EPS_    1e-4f

__device__ float g_qnorm[NROWS_];
__device__ float g_knorm[NROWS_];
__device__ float g_kpart[2048];
__device__ float g_kmaxf;
__device__ float g_ctxT[B_ * D_ * MP_];   // [b][e][m]
__device__ float g_ksum[B_ * MP_];

// ---------------- helpers ----------------
__device__ __forceinline__ void mma_bf16(float* d, const uint32_t* a,
                                         uint32_t b0, uint32_t b1) {
    asm volatile(
        "mma.sync.aligned.m16n8k16.row.col.f32.bf16.bf16.f32 "
        "{%0,%1,%2,%3}, {%4,%5,%6,%7}, {%8,%9}, {%0,%1,%2,%3};\n"
        : "+f"(d[0]), "+f"(d[1]), "+f"(d[2]), "+f"(d[3])
        : "r"(a[0]), "r"(a[1]), "r"(a[2]), "r"(a[3]), "r"(b0), "r"(b1));
}
__device__ __forceinline__ void split_pack(float x, float y, uint32_t& hi, uint32_t& lo) {
    __nv_bfloat16 hx = __float2bfloat16(x);
    __nv_bfloat16 hy = __float2bfloat16(y);
    __nv_bfloat16 lx = __float2bfloat16(x - __bfloat162float(hx));
    __nv_bfloat16 ly = __float2bfloat16(y - __bfloat162float(hy));
    hi = (uint32_t)__bfloat16_as_ushort(hx) | ((uint32_t)__bfloat16_as_ushort(hy) << 16);
    lo = (uint32_t)__bfloat16_as_ushort(lx) | ((uint32_t)__bfloat16_as_ushort(ly) << 16);
}
__device__ __forceinline__ uint32_t fenc(float x) {
    uint32_t u = __float_as_uint(x);
    return (u & 0x80000000u) ? ~u : (u | 0x80000000u);
}
__device__ __forceinline__ float fdec(uint32_t u) {
    return (u & 0x80000000u) ? __uint_as_float(u & 0x7FFFFFFFu) : __uint_as_float(~u);
}

// ---------------- K0: zero accumulators (graph replays!) ----------------
__global__ void k0_zero() {
    int i = blockIdx.x * 256 + threadIdx.x;
    if (i < B_ * D_ * MP_) g_ctxT[i] = 0.f;
    if (i < B_ * MP_) g_ksum[i] = 0.f;
}

// ---------------- norms ----------------
__global__ void knorms(const float* __restrict__ q, const float* __restrict__ k) {
    const int warp = threadIdx.x >> 5, lane = threadIdx.x & 31;
    const bool isq = blockIdx.x < 16384;
    const int row = (isq ? blockIdx.x : blockIdx.x - 16384) * 8 + warp;
    const float2 v = ((const float2*)((isq ? q : k) + (size_t)row * 64))[lane];
    float s = v.x * v.x + v.y * v.y;
#pragma unroll
    for (int o = 16; o; o >>= 1) s += __shfl_xor_sync(0xffffffffu, s, o);
    if (!lane) (isq ? g_qnorm : g_knorm)[row] = NORMC_ * s;
}

// ---------------- KA: global max of k @ P^T (values discarded) ------------------
#define KA_AH 0
#define KA_AL 18432
#define KA_BH 36864
#define KA_BL 57600
#define KA_WM 78336
#define KA_SM 78400

__global__ __launch_bounds__(256)
void ka_kmax(const float* __restrict__ K, const float* __restrict__ P) {
    extern __shared__ char sm[];
    uint32_t* Ah = (uint32_t*)(sm + KA_AH);
    uint32_t* Al = (uint32_t*)(sm + KA_AL);
    uint32_t* Bh = (uint32_t*)(sm + KA_BH);
    uint32_t* Bl = (uint32_t*)(sm + KA_BL);
    float* wmax = (float*)(sm + KA_WM);

    const int tid = threadIdx.x, w = tid >> 5, l = tid & 31;
    const int g = l >> 2, t = l & 3;
    const int row0 = blockIdx.x * 128;
    const int m0 = blockIdx.y * 144;
    const int r_off = (w & 3) * 32;
    const int f_off = (w >> 2) * 72;

    const float4* X4 = (const float4*)K;
    for (int i = tid; i < 2048; i += 256) {
        const int r = i >> 4, c4 = i & 15;
        float4 v = X4[(size_t)(row0 + r) * 16 + c4];
        uint32_t h0, l0, h1, l1;
        split_pack(v.x, v.y, h0, l0);
        split_pack(v.z, v.w, h1, l1);
        Ah[r * 36 + 2 * c4] = h0; Ah[r * 36 + 2 * c4 + 1] = h1;
        Al[r * 36 + 2 * c4] = l0; Al[r * 36 + 2 * c4 + 1] = l1;
    }
    const float4* P4 = (const float4*)P;
    for (int i = tid; i < 2304; i += 256) {
        const int m = i >> 4, c4 = i & 15;
        float4 v = make_float4(0.f, 0.f, 0.f, 0.f);
        if (m0 + m < M_) v = P4[(size_t)(m0 + m) * 16 + c4];
        uint32_t h0, l0, h1, l1;
        split_pack(v.x * SCALE_, v.y * SCALE_, h0, l0);
        split_pack(v.z * SCALE_, v.w * SCALE_, h1, l1);
        Bh[m * 36 + 2 * c4] = h0; Bh[m * 36 + 2 * c4 + 1] = h1;
        Bl[m * 36 + 2 * c4] = l0; Bl[m * 36 + 2 * c4 + 1] = l1;
    }
    __syncthreads();

    float acc[2][9][4];
#pragma unroll
    for (int mi = 0; mi < 2; mi++)
#pragma unroll
        for (int ni = 0; ni < 9; ni++)
#pragma unroll
            for (int j = 0; j < 4; j++) acc[mi][ni][j] = 0.f;

#pragma unroll
    for (int kk = 0; kk < 4; kk++) {
        const int c = 8 * kk + t;
        uint32_t ah[2][4], al[2][4];
#pragma unroll
        for (int mi = 0; mi < 2; mi++) {
            const int rA = r_off + 16 * mi;
            ah[mi][0] = Ah[(rA + g) * 36 + c];
            ah[mi][1] = Ah[(rA + 8 + g) * 36 + c];
            ah[mi][2] = Ah[(rA + g) * 36 + c + 4];
            ah[mi][3] = Ah[(rA + 8 + g) * 36 + c + 4];
            al[mi][0] = Al[(rA + g) * 36 + c];
            al[mi][1] = Al[(rA + 8 + g) * 36 + c];
            al[mi][2] = Al[(rA + g) * 36 + c + 4];
            al[mi][3] = Al[(rA + 8 + g) * 36 + c + 4];
        }
#pragma unroll
        for (int ni = 0; ni < 9; ni++) {
            const int cw = (f_off + 8 * ni + g) * 36;
            uint32_t bh0 = Bh[cw + c], bh1 = Bh[cw + c + 4];
            uint32_t bl0 = Bl[cw + c], bl1 = Bl[cw + c + 4];
#pragma unroll
            for (int mi = 0; mi < 2; mi++) {
                mma_bf16(acc[mi][ni], ah[mi], bh0, bh1);
                mma_bf16(acc[mi][ni], ah[mi], bl0, bl1);
                mma_bf16(acc[mi][ni], al[mi], bh0, bh1);
            }
        }
    }

    float mx = -3.4e38f;
#pragma unroll
    for (int mi = 0; mi < 2; mi++)
#pragma unroll
        for (int ni = 0; ni < 9; ni++) {
            const int cb = m0 + f_off + 8 * ni + 2 * t;
            if (cb < M_) mx = fmaxf(mx, fmaxf(acc[mi][ni][0], acc[mi][ni][2]));
            if (cb + 1 < M_) mx = fmaxf(mx, fmaxf(acc[mi][ni][1], acc[mi][ni][3]));
        }
#pragma unroll
    for (int o = 16; o; o >>= 1) mx = fmaxf(mx, __shfl_xor_sync(0xffffffffu, mx, o));
    if (!l) wmax[w] = mx;
    __syncthreads();
    if (tid == 0) {
        float m2 = wmax[0];
#pragma unroll
        for (int i = 1; i < 8; i++) m2 = fmaxf(m2, wmax[i]);
        g_kpart[blockIdx.y * 1024 + blockIdx.x] = m2;
    }
}

__global__ void k1c_kmax() {
    __shared__ float sm[256];
    float mx = -3.4e38f;
    for (int i = threadIdx.x; i < 2048; i += 256) mx = fmaxf(mx, g_kpart[i]);
    sm[threadIdx.x] = mx;
    __syncthreads();
    for (int s = 128; s; s >>= 1) {
        if (threadIdx.x < s) sm[threadIdx.x] = fmaxf(sm[threadIdx.x], sm[threadIdx.x + s]);
        __syncthreads();
    }
    if (threadIdx.x == 0) g_kmaxf = sm[0];
}

// ---------------- KB: fused kdash-recompute + exp + ctxT GEMM -------------------
// CTA: (b, m-chunk 96, n-chunk 512). 256 thr. 8 n-subchunks of 64.
#define KB_PH  0         // 96*36*4 = 13824
#define KB_PL  13824
#define KB_KH  27648     // 64*36*4 = 9216
#define KB_KL  36864
#define KB_VH  46080     // 9216
#define KB_VL  55296
#define KB_BH  64512     // 13824
#define KB_BL  78336
#define KB_KPF 92160     // 64*98*4 = 25088
#define KB_KN  117248    // 256
#define KB_KS  117504    // 384
#define KB_SM  117888

__global__ __launch_bounds__(256)
void kb_ctx(const float* __restrict__ K, const float* __restrict__ V,
            const float* __restrict__ P) {
    extern __shared__ char sm[];
    uint32_t* Ph = (uint32_t*)(sm + KB_PH);
    uint32_t* Pl = (uint32_t*)(sm + KB_PL);
    uint32_t* Kh = (uint32_t*)(sm + KB_KH);
    uint32_t* Kl = (uint32_t*)(sm + KB_KL);
    uint32_t* Vh = (uint32_t*)(sm + KB_VH);
    uint32_t* Vl = (uint32_t*)(sm + KB_VL);
    uint32_t* Bh = (uint32_t*)(sm + KB_BH);
    uint32_t* Bl = (uint32_t*)(sm + KB_BL);
    float* kpf = (float*)(sm + KB_KPF);
    float* kn  = (float*)(sm + KB_KN);
    float* kss = (float*)(sm + KB_KS);

    const int tid = threadIdx.x, w = tid >> 5, l = tid & 31;
    const int g = l >> 2, t = l & 3;
    const int b = blockIdx.z;
    const int m0 = blockIdx.x * 96;
    const int nbase = blockIdx.y * 512;
    const int bN = b * N_;
    const float kmax = g_kmaxf;

    // GEMM1 warp mapping (out: 64 n x 96 m)
    const int w_n = w & 3, w_m = w >> 2;
    const int rA1 = 16 * w_n, fB1 = 48 * w_m;
    // GEMM2 warp mapping (out: 64 e x 96 m)
    const int w_e = w & 1, w_m2 = w >> 1;
    const int rA2 = 32 * w_e, fB2 = 24 * w_m2;
    // v staging mapping
    const int sv_e = l + 32 * (w & 1);
    const int sv_i0 = 8 * (w >> 1);

    // stage P chunk once
    const float4* P4 = (const float4*)P;
    for (int i = tid; i < 1536; i += 256) {
        const int m = i >> 4, c4 = i & 15;
        float4 v = make_float4(0.f, 0.f, 0.f, 0.f);
        if (m0 + m < M_) v = P4[(size_t)(m0 + m) * 16 + c4];
        uint32_t h0, l0, h1, l1;
        split_pack(v.x * SCALE_, v.y * SCALE_, h0, l0);
        split_pack(v.z * SCALE_, v.w * SCALE_, h1, l1);
        Ph[m * 36 + 2 * c4] = h0; Ph[m * 36 + 2 * c4 + 1] = h1;
        Pl[m * 36 + 2 * c4] = l0; Pl[m * 36 + 2 * c4 + 1] = l1;
    }
    if (tid < 96) kss[tid] = 0.f;

    float acc2[2][3][4];
#pragma unroll
    for (int mi = 0; mi < 2; mi++)
#pragma unroll
        for (int ni = 0; ni < 3; ni++)
#pragma unroll
            for (int j = 0; j < 4; j++) acc2[mi][ni][j] = 0.f;
    float ks[6][2];
#pragma unroll
    for (int ni = 0; ni < 6; ni++) { ks[ni][0] = 0.f; ks[ni][1] = 0.f; }

    const float4* K4 = (const float4*)K;

    for (int sc = 0; sc < 8; sc++) {
        const int n0 = nbase + sc * 64;
        __syncthreads();   // protect staging buffers from previous iteration
        // stage k rows
        for (int i = tid; i < 1024; i += 256) {
            const int r = i >> 4, c4 = i & 15;
            float4 v = K4[(size_t)(bN + n0 + r) * 16 + c4];
            uint32_t h0, l0, h1, l1;
            split_pack(v.x, v.y, h0, l0);
            split_pack(v.z, v.w, h1, l1);
            Kh[r * 36 + 2 * c4] = h0; Kh[r * 36 + 2 * c4 + 1] = h1;
            Kl[r * 36 + 2 * c4] = l0; Kl[r * 36 + 2 * c4 + 1] = l1;
        }
        // stage v (A for GEMM2): [e][n-pair]
#pragma unroll
        for (int ii = 0; ii < 8; ii++) {
            const int i = sv_i0 + ii;
            const int n = n0 + 2 * i;
            float v0 = V[(size_t)(bN + n) * 64 + sv_e];
            float v1 = V[(size_t)(bN + n + 1) * 64 + sv_e];
            uint32_t h, lo;
            split_pack(v0, v1, h, lo);
            Vh[sv_e * 36 + i] = h; Vl[sv_e * 36 + i] = lo;
        }
        if (tid < 64) kn[tid] = g_knorm[bN + n0 + tid];
        __syncthreads();

        // GEMM1: kdash chunk = k @ P^T
        float acc1[6][4];
#pragma unroll
        for (int ni = 0; ni < 6; ni++)
#pragma unroll
            for (int j = 0; j < 4; j++) acc1[ni][j] = 0.f;
#pragma unroll
        for (int kk = 0; kk < 4; kk++) {
            const int c = 8 * kk + t;
            uint32_t ah[4], al[4];
            ah[0] = Kh[(rA1 + g) * 36 + c];
            ah[1] = Kh[(rA1 + 8 + g) * 36 + c];
            ah[2] = Kh[(rA1 + g) * 36 + c + 4];
            ah[3] = Kh[(rA1 + 8 + g) * 36 + c + 4];
            al[0] = Kl[(rA1 + g) * 36 + c];
            al[1] = Kl[(rA1 + 8 + g) * 36 + c];
            al[2] = Kl[(rA1 + g) * 36 + c + 4];
            al[3] = Kl[(rA1 + 8 + g) * 36 + c + 4];
#pragma unroll
            for (int ni = 0; ni < 6; ni++) {
                const int cw = (fB1 + 8 * ni + g) * 36;
                uint32_t bh0 = Ph[cw + c], bh1 = Ph[cw + c + 4];
                uint32_t bl0 = Pl[cw + c], bl1 = Pl[cw + c + 4];
                mma_bf16(acc1[ni], ah, bh0, bh1);
                mma_bf16(acc1[ni], ah, bl0, bl1);
                mma_bf16(acc1[ni], al, bh0, bh1);
            }
        }
        // exp -> kp (fp32 smem), ksum partials
        {
            const int r0l = rA1 + g, r1l = r0l + 8;
            const float nm0 = kn[r0l], nm1 = kn[r1l];
#pragma unroll
            for (int ni = 0; ni < 6; ni++) {
                const int cL = fB1 + 8 * ni + 2 * t;
                const int mg = m0 + cL;
                float kp00 = (mg < M_) ? RATIO_ * (__expf(acc1[ni][0] - nm0 - kmax) + EPS_) : 0.f;
                float kp01 = (mg + 1 < M_) ? RATIO_ * (__expf(acc1[ni][1] - nm0 - kmax) + EPS_) : 0.f;
                float kp10 = (mg < M_) ? RATIO_ * (__expf(acc1[ni][2] - nm1 - kmax) + EPS_) : 0.f;
                float kp11 = (mg + 1 < M_) ? RATIO_ * (__expf(acc1[ni][3] - nm1 - kmax) + EPS_) : 0.f;
                ks[ni][0] += kp00 + kp10;
                ks[ni][1] += kp01 + kp11;
                *(float2*)&kpf[r0l * 98 + cL] = make_float2(kp00, kp01);
                *(float2*)&kpf[r1l * 98 + cL] = make_float2(kp10, kp11);
            }
        }
        __syncthreads();
        // repack kp -> split bf16 B operand [m][n-pair]
#pragma unroll
        for (int mm = 0; mm < 12; mm++) {
            const int m = 12 * w + mm;
            float x0 = kpf[(2 * l) * 98 + m];
            float x1 = kpf[(2 * l + 1) * 98 + m];
            uint32_t h, lo;
            split_pack(x0, x1, h, lo);
            Bh[m * 36 + l] = h; Bl[m * 36 + l] = lo;
        }
        __syncthreads();
        // GEMM2: ctxT += v^T @ kp
#pragma unroll
        for (int kk = 0; kk < 4; kk++) {
            const int c = 8 * kk + t;
            uint32_t ah[2][4], al[2][4];
#pragma unroll
            for (int mi = 0; mi < 2; mi++) {
                const int rA = rA2 + 16 * mi;
                ah[mi][0] = Vh[(rA + g) * 36 + c];
                ah[mi][1] = Vh[(rA + 8 + g) * 36 + c];
                ah[mi][2] = Vh[(rA + g) * 36 + c + 4];
                ah[mi][3] = Vh[(rA + 8 + g) * 36 + c + 4];
                al[mi][0] = Vl[(rA + g) * 36 + c];
                al[mi][1] = Vl[(rA + 8 + g) * 36 + c];
                al[mi][2] = Vl[(rA + g) * 36 + c + 4];
                al[mi][3] = Vl[(rA + 8 + g) * 36 + c + 4];
            }
#pragma unroll
            for (int ni = 0; ni < 3; ni++) {
                const int cw = (fB2 + 8 * ni + g) * 36;
                uint32_t bh0 = Bh[cw + c], bh1 = Bh[cw + c + 4];
                uint32_t bl0 = Bl[cw + c], bl1 = Bl[cw + c + 4];
#pragma unroll
                for (int mi = 0; mi < 2; mi++) {
                    mma_bf16(acc2[mi][ni], ah[mi], bh0, bh1);
                    mma_bf16(acc2[mi][ni], ah[mi], bl0, bl1);
                    mma_bf16(acc2[mi][ni], al[mi], bh0, bh1);
                }
            }
        }
    }

    // ksum -> smem -> global
    __syncthreads();
#pragma unroll
    for (int ni = 0; ni < 6; ni++) {
        const int col = fB1 + 8 * ni + 2 * t;
        atomicAdd(&kss[col], ks[ni][0]);
        atomicAdd(&kss[col + 1], ks[ni][1]);
    }
    __syncthreads();
    if (tid < 96 && m0 + tid < M_) atomicAdd(&g_ksum[b * MP_ + m0 + tid], kss[tid]);

    // ctxT atomics
#pragma unroll
    for (int mi = 0; mi < 2; mi++) {
        const int e0 = rA2 + 16 * mi + g;
#pragma unroll
        for (int ni = 0; ni < 3; ni++) {
            const int mc = m0 + fB2 + 8 * ni + 2 * t;
            float* p0 = &g_ctxT[((size_t)(b * 64 + e0)) * MP_ + mc];
            float* p1 = &g_ctxT[((size_t)(b * 64 + e0 + 8)) * MP_ + mc];
            atomicAdd(p0, acc2[mi][ni][0]);
            atomicAdd(p0 + 1, acc2[mi][ni][1]);
            atomicAdd(p1, acc2[mi][ni][2]);
            atomicAdd(p1 + 1, acc2[mi][ni][3]);
        }
    }
}

// ---------------- KC: fused qdash + exp + D + output GEMM -----------------------
// CTA: 64 q rows. Phase1 qdash=q@P^T (3 chunks of 96), phase2 exp+D, phase3 out.
#define KC_QAH 0          // 64*36*4 = 9216
#define KC_QAL 9216
#define KC_PH  18432      // 96*36*4 = 13824
#define KC_PL  32256
#define KC_QD  46080      // 64*292*4 = 74752 (reused: CBh/CBl 2x 64*146*4)
#define KC_CBH 46080
#define KC_CBL 83456
#define KC_QPH 120832     // 64*146*4 = 37376
#define KC_QPL 158208
#define KC_RM  195584     // 256
#define KC_DI  195840     // 256
#define KC_QN  196096     // 256
#define KC_SM  196352

__global__ __launch_bounds__(256)
void kc_out(const float* __restrict__ Q, const float* __restrict__ P,
            float* __restrict__ out) {
    extern __shared__ char sm[];
    uint32_t* QAh = (uint32_t*)(sm + KC_QAH);
    uint32_t* QAl = (uint32_t*)(sm + KC_QAL);
    uint32_t* Ph  = (uint32_t*)(sm + KC_PH);
    uint32_t* Pl  = (uint32_t*)(sm + KC_PL);
    float*    qdf = (float*)(sm + KC_QD);
    uint32_t* CBh = (uint32_t*)(sm + KC_CBH);
    uint32_t* CBl = (uint32_t*)(sm + KC_CBL);
    uint32_t* QPh = (uint32_t*)(sm + KC_QPH);
    uint32_t* QPl = (uint32_t*)(sm + KC_QPL);
    uint32_t* rmU = (uint32_t*)(sm + KC_RM);
    float*    dinv = (float*)(sm + KC_DI);
    float*    qn_s = (float*)(sm + KC_QN);

    const int tid = threadIdx.x, w = tid >> 5, l = tid & 31;
    const int g = l >> 2, t = l & 3;
    const int b = blockIdx.y;
    const int r0 = blockIdx.x * 64;
    const int bN = b * N_;

    // stage q rows (once)
    const float4* Q4 = (const float4*)Q;
    for (int i = tid; i < 1024; i += 256) {
        const int r = i >> 4, c4 = i & 15;
        float4 v = Q4[(size_t)(bN + r0 + r) * 16 + c4];
        uint32_t h0, l0, h1, l1;
        split_pack(v.x, v.y, h0, l0);
        split_pack(v.z, v.w, h1, l1);
        QAh[r * 36 + 2 * c4] = h0; QAh[r * 36 + 2 * c4 + 1] = h1;
        QAl[r * 36 + 2 * c4] = l0; QAl[r * 36 + 2 * c4 + 1] = l1;
    }
    if (tid < 64) { qn_s[tid] = g_qnorm[bN + r0 + tid]; rmU[tid] = 0u; }

    const int w_r = w & 3, w_m = w >> 2;
    const int rA = 16 * w_r, fB = 48 * w_m;
    float rmx0 = -3.4e38f, rmx1 = -3.4e38f;

    const float4* P4 = (const float4*)P;
    for (int mc = 0; mc < 3; mc++) {
        __syncthreads();
        for (int i = tid; i < 1536; i += 256) {
            const int m = i >> 4, c4 = i & 15;
            float4 v = make_float4(0.f, 0.f, 0.f, 0.f);
            if (96 * mc + m < M_) v = P4[(size_t)(96 * mc + m) * 16 + c4];
            uint32_t h0, l0, h1, l1;
            split_pack(v.x * SCALE_, v.y * SCALE_, h0, l0);
            split_pack(v.z * SCALE_, v.w * SCALE_, h1, l1);
            Ph[m * 36 + 2 * c4] = h0; Ph[m * 36 + 2 * c4 + 1] = h1;
            Pl[m * 36 + 2 * c4] = l0; Pl[m * 36 + 2 * c4 + 1] = l1;
        }
        __syncthreads();

        float acc[6][4];
#pragma unroll
        for (int ni = 0; ni < 6; ni++)
#pragma unroll
            for (int j = 0; j < 4; j++) acc[ni][j] = 0.f;
#pragma unroll
        for (int kk = 0; kk < 4; kk++) {
            const int c = 8 * kk + t;
            uint32_t ah[4], al[4];
            ah[0] = QAh[(rA + g) * 36 + c];
            ah[1] = QAh[(rA + 8 + g) * 36 + c];
            ah[2] = QAh[(rA + g) * 36 + c + 4];
            ah[3] = QAh[(rA + 8 + g) * 36 + c + 4];
            al[0] = QAl[(rA + g) * 36 + c];
            al[1] = QAl[(rA + 8 + g) * 36 + c];
            al[2] = QAl[(rA + g) * 36 + c + 4];
            al[3] = QAl[(rA + 8 + g) * 36 + c + 4];
#pragma unroll
            for (int ni = 0; ni < 6; ni++) {
                const int cw = (fB + 8 * ni + g) * 36;
                uint32_t bh0 = Ph[cw + c], bh1 = Ph[cw + c + 4];
                uint32_t bl0 = Pl[cw + c], bl1 = Pl[cw + c + 4];
                mma_bf16(acc[ni], ah, bh0, bh1);
                mma_bf16(acc[ni], ah, bl0, bl1);
                mma_bf16(acc[ni], al, bh0, bh1);
            }
        }
#pragma unroll
        for (int ni = 0; ni < 6; ni++) {
            const int cL = fB + 8 * ni + 2 * t;
            const int mg = 96 * mc + cL;
            *(float2*)&qdf[(rA + g) * 292 + mg] = make_float2(acc[ni][0], acc[ni][1]);
            *(float2*)&qdf[(rA + 8 + g) * 292 + mg] = make_float2(acc[ni][2], acc[ni][3]);
            if (mg < M_) { rmx0 = fmaxf(rmx0, acc[ni][0]); rmx1 = fmaxf(rmx1, acc[ni][2]); }
            if (mg + 1 < M_) { rmx0 = fmaxf(rmx0, acc[ni][1]); rmx1 = fmaxf(rmx1, acc[ni][3]); }
        }
    }
    atomicMax(&rmU[rA + g], fenc(rmx0));
    atomicMax(&rmU[rA + 8 + g], fenc(rmx1));
    __syncthreads();

    // phase2: exp + D + pack qp
    {
        const int r = tid >> 2, q4 = tid & 3;
        const float qn = qn_s[r];
        const float qm = fdec(rmU[r]);
        const float* ksp = g_ksum + b * MP_;
        float Dp = 0.f;
#pragma unroll
        for (int j = 0; j < 18; j++) {
            const int mb = 72 * q4 + 4 * j;
            float4 d = *(float4*)&qdf[r * 292 + mb];
            float4 ks4 = *(const float4*)&ksp[mb];
            float q0 = (mb < M_) ? RATIO_ * (__expf(d.x - qn - qm) + EPS_) : 0.f;
            float q1 = (mb + 1 < M_) ? RATIO_ * (__expf(d.y - qn - qm) + EPS_) : 0.f;
            float q2 = (mb + 2 < M_) ? RATIO_ * (__expf(d.z - qn - qm) + EPS_) : 0.f;
            float q3 = (mb + 3 < M_) ? RATIO_ * (__expf(d.w - qn - qm) + EPS_) : 0.f;
            Dp += q0 * ks4.x + q1 * ks4.y + q2 * ks4.z + q3 * ks4.w;
            uint32_t h0, l0, h1, l1;
            split_pack(q0, q1, h0, l0);
            split_pack(q2, q3, h1, l1);
            const int p = 36 * q4 + 2 * j;
            QPh[r * 146 + p] = h0; QPh[r * 146 + p + 1] = h1;
            QPl[r * 146 + p] = l0; QPl[r * 146 + p + 1] = l1;
        }
        Dp += __shfl_xor_sync(0xffffffffu, Dp, 1);
        Dp += __shfl_xor_sync(0xffffffffu, Dp, 2);
        if (q4 == 0) dinv[r] = 1.f / Dp;
    }
    __syncthreads();

    // phase3: stage ctxT (overwrites qdf region)
    {
        const int e = tid >> 2, q4 = tid & 3;
        const float* src = g_ctxT + ((size_t)(b * 64 + e)) * MP_;
#pragma unroll
        for (int j = 0; j < 18; j++) {
            const int mo = 72 * q4 + 4 * j;
            float4 cv = *(const float4*)&src[mo];
            uint32_t h0, l0, h1, l1;
            split_pack(cv.x, cv.y, h0, l0);
            split_pack(cv.z, cv.w, h1, l1);
            const int p = 36 * q4 + 2 * j;
            CBh[e * 146 + p] = h0; CBh[e * 146 + p + 1] = h1;
            CBl[e * 146 + p] = l0; CBl[e * 146 + p + 1] = l1;
        }
    }
    __syncthreads();

    // GEMM3: out = qp @ ctxT^T
    const int w_r3 = w & 3, w_e = w >> 2;
    const int rA3 = 16 * w_r3, eB = 32 * w_e;
    float acc3[4][4];
#pragma unroll
    for (int ni = 0; ni < 4; ni++)
#pragma unroll
        for (int j = 0; j < 4; j++) acc3[ni][j] = 0.f;
#pragma unroll
    for (int kk = 0; kk < 18; kk++) {
        const int c = 8 * kk + t;
        uint32_t ah[4], al[4];
        ah[0] = QPh[(rA3 + g) * 146 + c];
        ah[1] = QPh[(rA3 + 8 + g) * 146 + c];
        ah[2] = QPh[(rA3 + g) * 146 + c + 4];
        ah[3] = QPh[(rA3 + 8 + g) * 146 + c + 4];
        al[0] = QPl[(rA3 + g) * 146 + c];
        al[1] = QPl[(rA3 + 8 + g) * 146 + c];
        al[2] = QPl[(rA3 + g) * 146 + c + 4];
        al[3] = QPl[(rA3 + 8 + g) * 146 + c + 4];
#pragma unroll
        for (int ni = 0; ni < 4; ni++) {
            const int cw = (eB + 8 * ni + g) * 146;
            uint32_t bh0 = CBh[cw + c], bh1 = CBh[cw + c + 4];
            uint32_t bl0 = CBl[cw + c], bl1 = CBl[cw + c + 4];
            mma_bf16(acc3[ni], ah, bh0, bh1);
            mma_bf16(acc3[ni], ah, bl0, bl1);
            mma_bf16(acc3[ni], al, bh0, bh1);
        }
    }
#pragma unroll
    for (int ni = 0; ni < 4; ni++) {
        const int row = rA3 + g;
        const int col = eB + 8 * ni + 2 * t;
        const float di0 = dinv[row], di1 = dinv[row + 8];
        *(float2*)&out[((size_t)(bN + r0 + row)) * 64 + col] =
            make_float2(acc3[ni][0] * di0, acc3[ni][1] * di0);
        *(float2*)&out[((size_t)(bN + r0 + row + 8)) * 64 + col] =
            make_float2(acc3[ni][2] * di1, acc3[ni][3] * di1);
    }
}

// ---------------- launcher ----------------
extern "C" void kernel_launch(void* const* d_in, const int* in_sizes, int n_in,
                              void* d_out, int out_size) {
    const float* q    = (const float*)d_in[0];
    const float* k    = (const float*)d_in[1];
    const float* v    = (const float*)d_in[2];
    const float* proj = (const float*)d_in[3];
    float* out = (float*)d_out;

    static int configured = 0;
    if (!configured) {
        cudaFuncSetAttribute(ka_kmax, cudaFuncAttributeMaxDynamicSharedMemorySize, KA_SM);
        cudaFuncSetAttribute(kb_ctx, cudaFuncAttributeMaxDynamicSharedMemorySize, KB_SM);
        cudaFuncSetAttribute(kc_out, cudaFuncAttributeMaxDynamicSharedMemorySize, KC_SM);
        configured = 1;
    }

    k0_zero<<<4608, 256>>>();
    knorms<<<32768, 256>>>(q, k);
    ka_kmax<<<dim3(1024, 2), 256, KA_SM>>>(k, proj);
    k1c_kmax<<<1, 256>>>();
    kb_ctx<<<dim3(3, 4, 64), 256, KB_SM>>>(k, v, proj);
    kc_out<<<dim3(32, 64), 256, KC_SM>>>(q, proj, out);
}

// round 5
// speedup vs baseline: 1.4374x; 1.4374x over previous
#include <cuda_runtime.h>
#include <cuda_bf16.h>
#include <cstdint>

// Performer (FAVOR+) attention via mma.sync bf16 (split hi/lo, 3-MMA) GEMMs.
// R3 topology + coalesced epilogues + register prefetch. B=64,N=2048,d=64,m=266.

#define B_      64
#define N_      2048
#define D_      64
#define M_      266
#define MP_     288
#define NROWS_  (B_ * N_)
#define SCALE_  0.35355339059327373f
#define NORMC_  0.0625f
#define RATIO_  0.06131393394849658f
#define EPS_    1e-4f

__device__ float    g_qdash[NROWS_ * MP_];
__device__ float    g_kdash[NROWS_ * MP_];
__device__ float    g_qnorm[NROWS_];
__device__ float    g_knorm[NROWS_];
__device__ uint32_t g_qmaxU[NROWS_];
__device__ float    g_kpart[2048];
__device__ float    g_kmaxf;
__device__ float    g_ctxT[B_ * D_ * MP_];   // [b][e][m]
__device__ float    g_ksum[B_ * MP_];

// ---------------- helpers ----------------
__device__ __forceinline__ void mma_bf16(float* d, const uint32_t* a,
                                         uint32_t b0, uint32_t b1) {
    asm volatile(
        "mma.sync.aligned.m16n8k16.row.col.f32.bf16.bf16.f32 "
        "{%0,%1,%2,%3}, {%4,%5,%6,%7}, {%8,%9}, {%0,%1,%2,%3};\n"
        : "+f"(d[0]), "+f"(d[1]), "+f"(d[2]), "+f"(d[3])
        : "r"(a[0]), "r"(a[1]), "r"(a[2]), "r"(a[3]), "r"(b0), "r"(b1));
}
__device__ __forceinline__ void split_pack(float x, float y, uint32_t& hi, uint32_t& lo) {
    __nv_bfloat16 hx = __float2bfloat16(x);
    __nv_bfloat16 hy = __float2bfloat16(y);
    __nv_bfloat16 lx = __float2bfloat16(x - __bfloat162float(hx));
    __nv_bfloat16 ly = __float2bfloat16(y - __bfloat162float(hy));
    hi = (uint32_t)__bfloat16_as_ushort(hx) | ((uint32_t)__bfloat16_as_ushort(hy) << 16);
    lo = (uint32_t)__bfloat16_as_ushort(lx) | ((uint32_t)__bfloat16_as_ushort(ly) << 16);
}
__device__ __forceinline__ uint32_t fenc(float x) {
    uint32_t u = __float_as_uint(x);
    return (u & 0x80000000u) ? ~u : (u | 0x80000000u);
}
__device__ __forceinline__ float fdec(uint32_t u) {
    return (u & 0x80000000u) ? __uint_as_float(u & 0x7FFFFFFFu) : __uint_as_float(~u);
}

// ---------------- K0: zero accumulators (graph replays!) ----------------
__global__ void k0_zero() {
    int i = blockIdx.x * 256 + threadIdx.x;
    if (i < B_ * D_ * MP_) g_ctxT[i] = 0.f;
    if (i < B_ * MP_) g_ksum[i] = 0.f;
    if (i < NROWS_) g_qmaxU[i] = 0u;
}

// ---------------- K1: dash = SCALE * X @ P^T (split-bf16 mma) ------------------
// CTA: 128 rows x 144 feats. 256 thr, 8 warps (4r x 2f), warp tile 32x72.
// Epilogue: acc -> smem (reusing A/B region) -> coalesced float4 stores.
#define K1_AH 0
#define K1_AL 18432
#define K1_BH 36864
#define K1_BL 57600
#define K1_RM 78336
#define K1_SM 78848

__global__ __launch_bounds__(256)
void k1_proj(const float* __restrict__ X, const float* __restrict__ P, int isq) {
    extern __shared__ char sm[];
    uint32_t* Ah = (uint32_t*)(sm + K1_AH);
    uint32_t* Al = (uint32_t*)(sm + K1_AL);
    uint32_t* Bh = (uint32_t*)(sm + K1_BH);
    uint32_t* Bl = (uint32_t*)(sm + K1_BL);
    float*    OB = (float*)sm;                     // union: used after MMA
    uint32_t* rmaxU = (uint32_t*)(sm + K1_RM);

    const int tid = threadIdx.x, w = tid >> 5, l = tid & 31;
    const int g = l >> 2, t = l & 3;
    const int row0 = blockIdx.x * 128;
    const int m0 = blockIdx.y * 144;
    const int r_off = (w & 3) * 32;
    const int f_off = (w >> 2) * 72;
    float* dash  = isq ? g_qdash : g_kdash;
    float* norms = isq ? g_qnorm : g_knorm;

    if (tid < 128) rmaxU[tid] = 0u;
    __syncthreads();

    const float4* X4 = (const float4*)X;
    for (int i = tid; i < 2048; i += 256) {
        const int r = i >> 4, c4 = i & 15;
        float4 v = X4[(size_t)(row0 + r) * 16 + c4];
        uint32_t h0, l0, h1, l1;
        split_pack(v.x, v.y, h0, l0);
        split_pack(v.z, v.w, h1, l1);
        Ah[r * 36 + 2 * c4] = h0; Ah[r * 36 + 2 * c4 + 1] = h1;
        Al[r * 36 + 2 * c4] = l0; Al[r * 36 + 2 * c4 + 1] = l1;
    }
    const float4* P4 = (const float4*)P;
    for (int i = tid; i < 2304; i += 256) {
        const int m = i >> 4, c4 = i & 15;
        float4 v = make_float4(0.f, 0.f, 0.f, 0.f);
        if (m0 + m < M_) v = P4[(size_t)(m0 + m) * 16 + c4];
        uint32_t h0, l0, h1, l1;
        split_pack(v.x * SCALE_, v.y * SCALE_, h0, l0);
        split_pack(v.z * SCALE_, v.w * SCALE_, h1, l1);
        Bh[m * 36 + 2 * c4] = h0; Bh[m * 36 + 2 * c4 + 1] = h1;
        Bl[m * 36 + 2 * c4] = l0; Bl[m * 36 + 2 * c4 + 1] = l1;
    }
    __syncthreads();

    // norms (L1-hot rows; only one feature-block computes them)
    if (blockIdx.y == 0 && tid < 128) {
        float s = 0.f;
        const float4* xr = X4 + (size_t)(row0 + tid) * 16;
#pragma unroll
        for (int c4 = 0; c4 < 16; c4++) {
            float4 v = xr[c4];
            s += v.x * v.x + v.y * v.y + v.z * v.z + v.w * v.w;
        }
        norms[row0 + tid] = NORMC_ * s;
    }

    float acc[2][9][4];
#pragma unroll
    for (int mi = 0; mi < 2; mi++)
#pragma unroll
        for (int ni = 0; ni < 9; ni++)
#pragma unroll
            for (int j = 0; j < 4; j++) acc[mi][ni][j] = 0.f;

#pragma unroll
    for (int kk = 0; kk < 4; kk++) {
        const int c = 8 * kk + t;
        uint32_t ah[2][4], al[2][4];
#pragma unroll
        for (int mi = 0; mi < 2; mi++) {
            const int rA = r_off + 16 * mi;
            ah[mi][0] = Ah[(rA + g) * 36 + c];
            ah[mi][1] = Ah[(rA + 8 + g) * 36 + c];
            ah[mi][2] = Ah[(rA + g) * 36 + c + 4];
            ah[mi][3] = Ah[(rA + 8 + g) * 36 + c + 4];
            al[mi][0] = Al[(rA + g) * 36 + c];
            al[mi][1] = Al[(rA + 8 + g) * 36 + c];
            al[mi][2] = Al[(rA + g) * 36 + c + 4];
            al[mi][3] = Al[(rA + 8 + g) * 36 + c + 4];
        }
#pragma unroll
        for (int ni = 0; ni < 9; ni++) {
            const int cw = (f_off + 8 * ni + g) * 36;
            uint32_t bh0 = Bh[cw + c], bh1 = Bh[cw + c + 4];
            uint32_t bl0 = Bl[cw + c], bl1 = Bl[cw + c + 4];
#pragma unroll
            for (int mi = 0; mi < 2; mi++) {
                mma_bf16(acc[mi][ni], ah[mi], bh0, bh1);
                mma_bf16(acc[mi][ni], ah[mi], bl0, bl1);
                mma_bf16(acc[mi][ni], al[mi], bh0, bh1);
            }
        }
    }

    // row maxes (masked to m < 266)
    float rmx[2][2] = {{-3.4e38f, -3.4e38f}, {-3.4e38f, -3.4e38f}};
#pragma unroll
    for (int mi = 0; mi < 2; mi++)
#pragma unroll
        for (int ni = 0; ni < 9; ni++) {
            const int cb = m0 + f_off + 8 * ni + 2 * t;
            if (cb < M_) {
                rmx[mi][0] = fmaxf(rmx[mi][0], acc[mi][ni][0]);
                rmx[mi][1] = fmaxf(rmx[mi][1], acc[mi][ni][2]);
            }
            if (cb + 1 < M_) {
                rmx[mi][0] = fmaxf(rmx[mi][0], acc[mi][ni][1]);
                rmx[mi][1] = fmaxf(rmx[mi][1], acc[mi][ni][3]);
            }
        }
#pragma unroll
    for (int mi = 0; mi < 2; mi++) {
        atomicMax(&rmaxU[r_off + 16 * mi + g], fenc(rmx[mi][0]));
        atomicMax(&rmaxU[r_off + 16 * mi + 8 + g], fenc(rmx[mi][1]));
    }

    __syncthreads();   // A/B fully consumed; OB may overwrite
    // acc -> smem buffer (stride 148 floats)
#pragma unroll
    for (int mi = 0; mi < 2; mi++) {
        const int rl = r_off + 16 * mi + g;
#pragma unroll
        for (int ni = 0; ni < 9; ni++) {
            const int cl = f_off + 8 * ni + 2 * t;
            *(float2*)&OB[rl * 148 + cl]       = make_float2(acc[mi][ni][0], acc[mi][ni][1]);
            *(float2*)&OB[(rl + 8) * 148 + cl] = make_float2(acc[mi][ni][2], acc[mi][ni][3]);
        }
    }
    __syncthreads();

    // coalesced dash store: 128 rows x 36 float4
    for (int i = tid; i < 4608; i += 256) {
        const int r = i / 36, c4 = i - 36 * r;
        *(float4*)&dash[(size_t)(row0 + r) * MP_ + m0 + 4 * c4] =
            *(float4*)&OB[r * 148 + 4 * c4];
    }

    if (isq) {
        if (tid < 128) atomicMax(&g_qmaxU[row0 + tid], rmaxU[tid]);
    } else {
        if (tid < 32) {
            uint32_t u = max(max(rmaxU[tid], rmaxU[tid + 32]),
                             max(rmaxU[tid + 64], rmaxU[tid + 96]));
#pragma unroll
            for (int o = 16; o; o >>= 1)
                u = max(u, __shfl_xor_sync(0xffffffffu, u, o));
            if (tid == 0) g_kpart[blockIdx.y * 1024 + blockIdx.x] = fdec(u);
        }
    }
}

// ---------------- K1c: global k max ----------------
__global__ void k1c_kmax() {
    __shared__ float sm[256];
    float mx = -3.4e38f;
    for (int i = threadIdx.x; i < 2048; i += 256) mx = fmaxf(mx, g_kpart[i]);
    sm[threadIdx.x] = mx;
    __syncthreads();
    for (int s = 128; s; s >>= 1) {
        if (threadIdx.x < s) sm[threadIdx.x] = fmaxf(sm[threadIdx.x], sm[threadIdx.x + s]);
        __syncthreads();
    }
    if (threadIdx.x == 0) g_kmaxf = sm[0];
}

// ---------------- K2: ctxT[e][m] += sum_n v[n,e]*kp[n,m] (prefetched) ----------
__global__ __launch_bounds__(192)
void k2_ctx(const float* __restrict__ v) {
    __shared__ uint32_t VAh[64 * 12], VAl[64 * 12];
    __shared__ uint32_t KBh[96 * 12], KBl[96 * 12];

    const int tid = threadIdx.x, w = tid >> 5, l = tid & 31;
    const int g = l >> 2, t = l & 3;
    const int b = blockIdx.z;
    const int m0 = blockIdx.x * 96;
    const int nbase = blockIdx.y * 512;
    const int bN = b * N_;
    const float kmax = g_kmaxf;

    const int mloc = l + 32 * (w % 3);
    const int sgrp = w / 3;
    const int mglob = m0 + mloc;
    const bool mval = mglob < M_;
    const int vg = w >> 1;                // v staging (w < 4)
    const int ve = l + 32 * (w & 1);

    const int e_off = (w & 1) * 32;
    const int m_off = (w >> 1) * 32;

    float acc[2][4][4];
#pragma unroll
    for (int mi = 0; mi < 2; mi++)
#pragma unroll
        for (int ni = 0; ni < 4; ni++)
#pragma unroll
            for (int j = 0; j < 4; j++) acc[mi][ni][j] = 0.f;
    float kslocal = 0.f;

    float pd0[4], pd1[4], pn0[4], pn1[4], pv0[4], pv1[4];
#pragma unroll
    for (int ii = 0; ii < 4; ii++) {
        const int n = nbase + 2 * (4 * sgrp + ii);
        pd0[ii] = g_kdash[(size_t)(bN + n) * MP_ + mglob];
        pd1[ii] = g_kdash[(size_t)(bN + n + 1) * MP_ + mglob];
        pn0[ii] = g_knorm[bN + n];
        pn1[ii] = g_knorm[bN + n + 1];
    }
    if (w < 4) {
#pragma unroll
        for (int ii = 0; ii < 4; ii++) {
            const int n = nbase + 2 * (4 * vg + ii);
            pv0[ii] = v[(size_t)(bN + n) * 64 + ve];
            pv1[ii] = v[(size_t)(bN + n + 1) * 64 + ve];
        }
    }

    for (int ck = 0; ck < 32; ck++) {
        float d0c[4], d1c[4], n0c[4], n1c[4], v0c[4], v1c[4];
#pragma unroll
        for (int ii = 0; ii < 4; ii++) {
            d0c[ii] = pd0[ii]; d1c[ii] = pd1[ii];
            n0c[ii] = pn0[ii]; n1c[ii] = pn1[ii];
            v0c[ii] = pv0[ii]; v1c[ii] = pv1[ii];
        }
        if (ck < 31) {
            const int nn = nbase + 16 * (ck + 1);
#pragma unroll
            for (int ii = 0; ii < 4; ii++) {
                const int n = nn + 2 * (4 * sgrp + ii);
                pd0[ii] = g_kdash[(size_t)(bN + n) * MP_ + mglob];
                pd1[ii] = g_kdash[(size_t)(bN + n + 1) * MP_ + mglob];
                pn0[ii] = g_knorm[bN + n];
                pn1[ii] = g_knorm[bN + n + 1];
            }
            if (w < 4) {
#pragma unroll
                for (int ii = 0; ii < 4; ii++) {
                    const int n = nn + 2 * (4 * vg + ii);
                    pv0[ii] = v[(size_t)(bN + n) * 64 + ve];
                    pv1[ii] = v[(size_t)(bN + n + 1) * 64 + ve];
                }
            }
        }
        // stage kp
#pragma unroll
        for (int ii = 0; ii < 4; ii++) {
            const int i = 4 * sgrp + ii;
            float kp0 = mval ? RATIO_ * (__expf(d0c[ii] - n0c[ii] - kmax) + EPS_) : 0.f;
            float kp1 = mval ? RATIO_ * (__expf(d1c[ii] - n1c[ii] - kmax) + EPS_) : 0.f;
            kslocal += kp0 + kp1;
            uint32_t h, lo;
            split_pack(kp0, kp1, h, lo);
            KBh[mloc * 12 + i] = h; KBl[mloc * 12 + i] = lo;
        }
        // stage v
        if (w < 4) {
#pragma unroll
            for (int ii = 0; ii < 4; ii++) {
                const int i = 4 * vg + ii;
                uint32_t h, lo;
                split_pack(v0c[ii], v1c[ii], h, lo);
                VAh[ve * 12 + i] = h; VAl[ve * 12 + i] = lo;
            }
        }
        __syncthreads();
        uint32_t ah[2][4], al[2][4];
#pragma unroll
        for (int mi = 0; mi < 2; mi++) {
            const int eR = e_off + 16 * mi;
            ah[mi][0] = VAh[(eR + g) * 12 + t];
            ah[mi][1] = VAh[(eR + 8 + g) * 12 + t];
            ah[mi][2] = VAh[(eR + g) * 12 + t + 4];
            ah[mi][3] = VAh[(eR + 8 + g) * 12 + t + 4];
            al[mi][0] = VAl[(eR + g) * 12 + t];
            al[mi][1] = VAl[(eR + 8 + g) * 12 + t];
            al[mi][2] = VAl[(eR + g) * 12 + t + 4];
            al[mi][3] = VAl[(eR + 8 + g) * 12 + t + 4];
        }
#pragma unroll
        for (int ni = 0; ni < 4; ni++) {
            const int cw = (m_off + 8 * ni + g) * 12;
            uint32_t bh0 = KBh[cw + t], bh1 = KBh[cw + t + 4];
            uint32_t bl0 = KBl[cw + t], bl1 = KBl[cw + t + 4];
#pragma unroll
            for (int mi = 0; mi < 2; mi++) {
                mma_bf16(acc[mi][ni], ah[mi], bh0, bh1);
                mma_bf16(acc[mi][ni], ah[mi], bl0, bl1);
                mma_bf16(acc[mi][ni], al[mi], bh0, bh1);
            }
        }
        __syncthreads();
    }

    if (mval && kslocal != 0.f) atomicAdd(&g_ksum[b * MP_ + mglob], kslocal);

#pragma unroll
    for (int mi = 0; mi < 2; mi++) {
        const int e0 = e_off + 16 * mi + g;
#pragma unroll
        for (int ni = 0; ni < 4; ni++) {
            const int mc = m0 + m_off + 8 * ni + 2 * t;
            float* p0 = &g_ctxT[((size_t)(b * 64 + e0)) * MP_ + mc];
            float* p1 = &g_ctxT[((size_t)(b * 64 + e0 + 8)) * MP_ + mc];
            atomicAdd(p0, acc[mi][ni][0]);
            atomicAdd(p0 + 1, acc[mi][ni][1]);
            atomicAdd(p1, acc[mi][ni][2]);
            atomicAdd(p1 + 1, acc[mi][ni][3]);
        }
    }
}

// ---------------- K3: out = (qp @ ctxT^T) * dinv (prefetched, coalesced) -------
#define K3_QPH 0
#define K3_QPL 10240
#define K3_CBH 20480
#define K3_CBL 25600
#define K3_DI  38912     // OB union occupies [0, 38912)
#define K3_SM  39424

__global__ __launch_bounds__(256)
void k3_out(float* __restrict__ out) {
    extern __shared__ char sm3[];
    uint32_t* QPh = (uint32_t*)(sm3 + K3_QPH);
    uint32_t* QPl = (uint32_t*)(sm3 + K3_QPL);
    uint32_t* CBh = (uint32_t*)(sm3 + K3_CBH);
    uint32_t* CBl = (uint32_t*)(sm3 + K3_CBL);
    float*    OB  = (float*)sm3;               // union after GEMM
    float*    dinv = (float*)(sm3 + K3_DI);

    const int tid = threadIdx.x, w = tid >> 5, l = tid & 31;
    const int g = l >> 2, t = l & 3;
    const int b = blockIdx.y;
    const int r0 = blockIdx.x * 128;
    const int bN = b * N_;

    const int sr = tid >> 1, shalf = tid & 1;
    const int se = tid >> 2, sq4 = tid & 3;

    const int gr = bN + r0 + sr;
    const float qn = g_qnorm[gr];
    const float qm = fdec(g_qmaxU[gr]);

    const int r_off = (w & 3) * 32;
    const int e_off = (w >> 2) * 32;

    float acc[2][4][4];
#pragma unroll
    for (int mi = 0; mi < 2; mi++)
#pragma unroll
        for (int ni = 0; ni < 4; ni++)
#pragma unroll
            for (int j = 0; j < 4; j++) acc[mi][ni][j] = 0.f;
    float Dpart = 0.f;

    const float* qsrc = g_qdash + (size_t)gr * MP_ + 16 * shalf;
    const float* csrc = g_ctxT + ((size_t)(b * 64 + se)) * MP_ + 8 * sq4;
    float4 pq[4], pc[2];
#pragma unroll
    for (int j = 0; j < 4; j++) pq[j] = *(const float4*)(qsrc + 4 * j);
#pragma unroll
    for (int j = 0; j < 2; j++) pc[j] = *(const float4*)(csrc + 4 * j);

    for (int ck = 0; ck < 9; ck++) {
        const int m0 = 32 * ck;
        float4 d[4], cc[2];
#pragma unroll
        for (int j = 0; j < 4; j++) d[j] = pq[j];
#pragma unroll
        for (int j = 0; j < 2; j++) cc[j] = pc[j];
        if (ck < 8) {
#pragma unroll
            for (int j = 0; j < 4; j++) pq[j] = *(const float4*)(qsrc + 32 * (ck + 1) + 4 * j);
#pragma unroll
            for (int j = 0; j < 2; j++) pc[j] = *(const float4*)(csrc + 32 * (ck + 1) + 4 * j);
        }
        // stage qp + D partial
        {
            const float* kss = g_ksum + b * MP_ + m0 + 16 * shalf;
#pragma unroll
            for (int j = 0; j < 4; j++) {
                float4 ks4 = *(const float4*)(kss + 4 * j);
                const int mb = m0 + 16 * shalf + 4 * j;
                float q0 = (mb < M_) ? RATIO_ * (__expf(d[j].x - qn - qm) + EPS_) : 0.f;
                float q1 = (mb + 1 < M_) ? RATIO_ * (__expf(d[j].y - qn - qm) + EPS_) : 0.f;
                float q2 = (mb + 2 < M_) ? RATIO_ * (__expf(d[j].z - qn - qm) + EPS_) : 0.f;
                float q3 = (mb + 3 < M_) ? RATIO_ * (__expf(d[j].w - qn - qm) + EPS_) : 0.f;
                Dpart += q0 * ks4.x + q1 * ks4.y + q2 * ks4.z + q3 * ks4.w;
                uint32_t h0, l0, h1, l1;
                split_pack(q0, q1, h0, l0);
                split_pack(q2, q3, h1, l1);
                const int i = 8 * shalf + 2 * j;
                QPh[sr * 20 + i] = h0; QPh[sr * 20 + i + 1] = h1;
                QPl[sr * 20 + i] = l0; QPl[sr * 20 + i + 1] = l1;
            }
        }
        // stage ctx
#pragma unroll
        for (int j = 0; j < 2; j++) {
            uint32_t h0, l0, h1, l1;
            split_pack(cc[j].x, cc[j].y, h0, l0);
            split_pack(cc[j].z, cc[j].w, h1, l1);
            const int i = 4 * sq4 + 2 * j;
            CBh[se * 20 + i] = h0; CBh[se * 20 + i + 1] = h1;
            CBl[se * 20 + i] = l0; CBl[se * 20 + i + 1] = l1;
        }
        __syncthreads();
#pragma unroll
        for (int kk = 0; kk < 2; kk++) {
            const int c = 8 * kk + t;
            uint32_t ah[2][4], al[2][4];
#pragma unroll
            for (int mi = 0; mi < 2; mi++) {
                const int rA = r_off + 16 * mi;
                ah[mi][0] = QPh[(rA + g) * 20 + c];
                ah[mi][1] = QPh[(rA + 8 + g) * 20 + c];
                ah[mi][2] = QPh[(rA + g) * 20 + c + 4];
                ah[mi][3] = QPh[(rA + 8 + g) * 20 + c + 4];
                al[mi][0] = QPl[(rA + g) * 20 + c];
                al[mi][1] = QPl[(rA + 8 + g) * 20 + c];
                al[mi][2] = QPl[(rA + g) * 20 + c + 4];
                al[mi][3] = QPl[(rA + 8 + g) * 20 + c + 4];
            }
#pragma unroll
            for (int ni = 0; ni < 4; ni++) {
                const int cw = (e_off + 8 * ni + g) * 20;
                uint32_t bh0 = CBh[cw + c], bh1 = CBh[cw + c + 4];
                uint32_t bl0 = CBl[cw + c], bl1 = CBl[cw + c + 4];
#pragma unroll
                for (int mi = 0; mi < 2; mi++) {
                    mma_bf16(acc[mi][ni], ah[mi], bh0, bh1);
                    mma_bf16(acc[mi][ni], ah[mi], bl0, bl1);
                    mma_bf16(acc[mi][ni], al[mi], bh0, bh1);
                }
            }
        }
        __syncthreads();
    }

    // finish D^-1
    Dpart += __shfl_xor_sync(0xffffffffu, Dpart, 1);
    if ((tid & 1) == 0) dinv[sr] = 1.f / Dpart;
    __syncthreads();

    // acc*dinv -> smem (stride 76), coalesced store
#pragma unroll
    for (int mi = 0; mi < 2; mi++) {
        const int rl0 = r_off + 16 * mi + g;
        const float di0 = dinv[rl0], di1 = dinv[rl0 + 8];
#pragma unroll
        for (int ni = 0; ni < 4; ni++) {
            const int col = e_off + 8 * ni + 2 * t;
            *(float2*)&OB[rl0 * 76 + col] =
                make_float2(acc[mi][ni][0] * di0, acc[mi][ni][1] * di0);
            *(float2*)&OB[(rl0 + 8) * 76 + col] =
                make_float2(acc[mi][ni][2] * di1, acc[mi][ni][3] * di1);
        }
    }
    __syncthreads();
    for (int i = tid; i < 2048; i += 256) {
        const int r = i >> 4, c4 = i & 15;
        *(float4*)&out[((size_t)(bN + r0 + r)) * 64 + 4 * c4] =
            *(float4*)&OB[r * 76 + 4 * c4];
    }
}

// ---------------- launcher ----------------
extern "C" void kernel_launch(void* const* d_in, const int* in_sizes, int n_in,
                              void* d_out, int out_size) {
    const float* q    = (const float*)d_in[0];
    const float* k    = (const float*)d_in[1];
    const float* v    = (const float*)d_in[2];
    const float* proj = (const float*)d_in[3];
    float* out = (float*)d_out;

    static int configured = 0;
    if (!configured) {
        cudaFuncSetAttribute(k1_proj, cudaFuncAttributeMaxDynamicSharedMemorySize, K1_SM);
        configured = 1;
    }

    k0_zero<<<4608, 256>>>();
    k1_proj<<<dim3(1024, 2), 256, K1_SM>>>(q, proj, 1);
    k1_proj<<<dim3(1024, 2), 256, K1_SM>>>(k, proj, 0);
    k1c_kmax<<<1, 256>>>();
    k2_ctx<<<dim3(3, 4, 64), 192>>>(v);
    k3_out<<<dim3(16, 64), 256, K3_SM>>>(out);
}

// round 6
// speedup vs baseline: 1.5688x; 1.0914x over previous
#include <cuda_runtime.h>
#include <cuda_bf16.h>
#include <cstdint>

// Performer (FAVOR+) attention via mma.sync bf16 (split hi/lo, 3-MMA) GEMMs.
// Atomic-free epilogues, double-buffered staging. B=64,N=2048,d=64,m=266(->288).

#define B_      64
#define N_      2048
#define D_      64
#define M_      266
#define MP_     288
#define NROWS_  (B_ * N_)
#define SCALE_  0.35355339059327373f
#define NORMC_  0.0625f
#define RATIO_  0.06131393394849658f
#define EPS_    1e-4f
#define CTXS_   ((size_t)B_ * 64 * MP_)

__device__ float    g_qdash[NROWS_ * MP_];
__device__ float    g_kdash[NROWS_ * MP_];
__device__ float    g_qnorm[NROWS_];
__device__ float    g_knorm[NROWS_];
__device__ float    g_qmax2[2 * NROWS_];       // per y-block row max
__device__ float    g_kpart[2048];
__device__ float    g_kmaxf;
__device__ float    g_ctxP[4 * B_ * 64 * MP_]; // per n-slice partial ctxT
__device__ float    g_ksumP[4 * B_ * MP_];     // per n-slice partial ksum

// ---------------- helpers ----------------
__device__ __forceinline__ void mma_bf16(float* d, const uint32_t* a,
                                         uint32_t b0, uint32_t b1) {
    asm volatile(
        "mma.sync.aligned.m16n8k16.row.col.f32.bf16.bf16.f32 "
        "{%0,%1,%2,%3}, {%4,%5,%6,%7}, {%8,%9}, {%0,%1,%2,%3};\n"
        : "+f"(d[0]), "+f"(d[1]), "+f"(d[2]), "+f"(d[3])
        : "r"(a[0]), "r"(a[1]), "r"(a[2]), "r"(a[3]), "r"(b0), "r"(b1));
}
__device__ __forceinline__ void split_pack(float x, float y, uint32_t& hi, uint32_t& lo) {
    __nv_bfloat16 hx = __float2bfloat16(x);
    __nv_bfloat16 hy = __float2bfloat16(y);
    __nv_bfloat16 lx = __float2bfloat16(x - __bfloat162float(hx));
    __nv_bfloat16 ly = __float2bfloat16(y - __bfloat162float(hy));
    hi = (uint32_t)__bfloat16_as_ushort(hx) | ((uint32_t)__bfloat16_as_ushort(hy) << 16);
    lo = (uint32_t)__bfloat16_as_ushort(lx) | ((uint32_t)__bfloat16_as_ushort(ly) << 16);
}
__device__ __forceinline__ uint32_t fenc(float x) {
    uint32_t u = __float_as_uint(x);
    return (u & 0x80000000u) ? ~u : (u | 0x80000000u);
}
__device__ __forceinline__ float fdec(uint32_t u) {
    return (u & 0x80000000u) ? __uint_as_float(u & 0x7FFFFFFFu) : __uint_as_float(~u);
}

// ---------------- K1: dash = SCALE * X @ P^T (q and k in one launch) -----------
#define K1_AH 0
#define K1_AL 18432
#define K1_BH 36864
#define K1_BL 57600
#define K1_RM 78336
#define K1_SM 78848

__global__ __launch_bounds__(256)
void k1_proj(const float* __restrict__ Q, const float* __restrict__ K,
             const float* __restrict__ P) {
    extern __shared__ char sm[];
    uint32_t* Ah = (uint32_t*)(sm + K1_AH);
    uint32_t* Al = (uint32_t*)(sm + K1_AL);
    uint32_t* Bh = (uint32_t*)(sm + K1_BH);
    uint32_t* Bl = (uint32_t*)(sm + K1_BL);
    float*    OB = (float*)sm;
    uint32_t* rmaxU = (uint32_t*)(sm + K1_RM);

    const int tid = threadIdx.x, w = tid >> 5, l = tid & 31;
    const int g = l >> 2, t = l & 3;
    const int isq = (blockIdx.z == 0);
    const float* X = isq ? Q : K;
    const int row0 = blockIdx.x * 128;
    const int m0 = blockIdx.y * 144;
    const int r_off = (w & 3) * 32;
    const int f_off = (w >> 2) * 72;
    float* dash  = isq ? g_qdash : g_kdash;
    float* norms = isq ? g_qnorm : g_knorm;

    if (tid < 128) rmaxU[tid] = 0u;
    __syncthreads();

    const float4* X4 = (const float4*)X;
    for (int i = tid; i < 2048; i += 256) {
        const int r = i >> 4, c4 = i & 15;
        float4 v = X4[(size_t)(row0 + r) * 16 + c4];
        uint32_t h0, l0, h1, l1;
        split_pack(v.x, v.y, h0, l0);
        split_pack(v.z, v.w, h1, l1);
        Ah[r * 36 + 2 * c4] = h0; Ah[r * 36 + 2 * c4 + 1] = h1;
        Al[r * 36 + 2 * c4] = l0; Al[r * 36 + 2 * c4 + 1] = l1;
    }
    const float4* P4 = (const float4*)P;
    for (int i = tid; i < 2304; i += 256) {
        const int m = i >> 4, c4 = i & 15;
        float4 v = make_float4(0.f, 0.f, 0.f, 0.f);
        if (m0 + m < M_) v = P4[(size_t)(m0 + m) * 16 + c4];
        uint32_t h0, l0, h1, l1;
        split_pack(v.x * SCALE_, v.y * SCALE_, h0, l0);
        split_pack(v.z * SCALE_, v.w * SCALE_, h1, l1);
        Bh[m * 36 + 2 * c4] = h0; Bh[m * 36 + 2 * c4 + 1] = h1;
        Bl[m * 36 + 2 * c4] = l0; Bl[m * 36 + 2 * c4 + 1] = l1;
    }
    __syncthreads();

    if (blockIdx.y == 0 && tid < 128) {
        float s = 0.f;
        const float4* xr = X4 + (size_t)(row0 + tid) * 16;
#pragma unroll
        for (int c4 = 0; c4 < 16; c4++) {
            float4 v = xr[c4];
            s += v.x * v.x + v.y * v.y + v.z * v.z + v.w * v.w;
        }
        norms[row0 + tid] = NORMC_ * s;
    }

    float acc[2][9][4];
#pragma unroll
    for (int mi = 0; mi < 2; mi++)
#pragma unroll
        for (int ni = 0; ni < 9; ni++)
#pragma unroll
            for (int j = 0; j < 4; j++) acc[mi][ni][j] = 0.f;

#pragma unroll
    for (int kk = 0; kk < 4; kk++) {
        const int c = 8 * kk + t;
        uint32_t ah[2][4], al[2][4];
#pragma unroll
        for (int mi = 0; mi < 2; mi++) {
            const int rA = r_off + 16 * mi;
            ah[mi][0] = Ah[(rA + g) * 36 + c];
            ah[mi][1] = Ah[(rA + 8 + g) * 36 + c];
            ah[mi][2] = Ah[(rA + g) * 36 + c + 4];
            ah[mi][3] = Ah[(rA + 8 + g) * 36 + c + 4];
            al[mi][0] = Al[(rA + g) * 36 + c];
            al[mi][1] = Al[(rA + 8 + g) * 36 + c];
            al[mi][2] = Al[(rA + g) * 36 + c + 4];
            al[mi][3] = Al[(rA + 8 + g) * 36 + c + 4];
        }
#pragma unroll
        for (int ni = 0; ni < 9; ni++) {
            const int cw = (f_off + 8 * ni + g) * 36;
            uint32_t bh0 = Bh[cw + c], bh1 = Bh[cw + c + 4];
            uint32_t bl0 = Bl[cw + c], bl1 = Bl[cw + c + 4];
#pragma unroll
            for (int mi = 0; mi < 2; mi++) {
                mma_bf16(acc[mi][ni], ah[mi], bh0, bh1);
                mma_bf16(acc[mi][ni], ah[mi], bl0, bl1);
                mma_bf16(acc[mi][ni], al[mi], bh0, bh1);
            }
        }
    }

    float rmx[2][2] = {{-3.4e38f, -3.4e38f}, {-3.4e38f, -3.4e38f}};
#pragma unroll
    for (int mi = 0; mi < 2; mi++)
#pragma unroll
        for (int ni = 0; ni < 9; ni++) {
            const int cb = m0 + f_off + 8 * ni + 2 * t;
            if (cb < M_) {
                rmx[mi][0] = fmaxf(rmx[mi][0], acc[mi][ni][0]);
                rmx[mi][1] = fmaxf(rmx[mi][1], acc[mi][ni][2]);
            }
            if (cb + 1 < M_) {
                rmx[mi][0] = fmaxf(rmx[mi][0], acc[mi][ni][1]);
                rmx[mi][1] = fmaxf(rmx[mi][1], acc[mi][ni][3]);
            }
        }
#pragma unroll
    for (int mi = 0; mi < 2; mi++) {
        atomicMax(&rmaxU[r_off + 16 * mi + g], fenc(rmx[mi][0]));
        atomicMax(&rmaxU[r_off + 16 * mi + 8 + g], fenc(rmx[mi][1]));
    }

    __syncthreads();
#pragma unroll
    for (int mi = 0; mi < 2; mi++) {
        const int rl = r_off + 16 * mi + g;
#pragma unroll
        for (int ni = 0; ni < 9; ni++) {
            const int cl = f_off + 8 * ni + 2 * t;
            *(float2*)&OB[rl * 148 + cl]       = make_float2(acc[mi][ni][0], acc[mi][ni][1]);
            *(float2*)&OB[(rl + 8) * 148 + cl] = make_float2(acc[mi][ni][2], acc[mi][ni][3]);
        }
    }
    __syncthreads();

    for (int i = tid; i < 4608; i += 256) {
        const int r = i / 36, c4 = i - 36 * r;
        *(float4*)&dash[(size_t)(row0 + r) * MP_ + m0 + 4 * c4] =
            *(float4*)&OB[r * 148 + 4 * c4];
    }

    if (isq) {
        if (tid < 128)
            g_qmax2[blockIdx.y * NROWS_ + row0 + tid] = fdec(rmaxU[tid]);
    } else {
        if (tid < 32) {
            uint32_t u = max(max(rmaxU[tid], rmaxU[tid + 32]),
                             max(rmaxU[tid + 64], rmaxU[tid + 96]));
#pragma unroll
            for (int o = 16; o; o >>= 1)
                u = max(u, __shfl_xor_sync(0xffffffffu, u, o));
            if (tid == 0) g_kpart[blockIdx.y * 1024 + blockIdx.x] = fdec(u);
        }
    }
}

// ---------------- K1c: global k max ----------------
__global__ void k1c_kmax() {
    __shared__ float sm[256];
    float mx = -3.4e38f;
    for (int i = threadIdx.x; i < 2048; i += 256) mx = fmaxf(mx, g_kpart[i]);
    sm[threadIdx.x] = mx;
    __syncthreads();
    for (int s = 128; s; s >>= 1) {
        if (threadIdx.x < s) sm[threadIdx.x] = fmaxf(sm[threadIdx.x], sm[threadIdx.x + s]);
        __syncthreads();
    }
    if (threadIdx.x == 0) g_kmaxf = sm[0];
}

// ---------------- K2: ctxP[slice] = v^T @ kp (double-buffered, STG) ------------
__global__ __launch_bounds__(192)
void k2_ctx(const float* __restrict__ v) {
    __shared__ uint32_t VAh[2][64 * 12], VAl[2][64 * 12];
    __shared__ uint32_t KBh[2][96 * 12], KBl[2][96 * 12];
    __shared__ float kss[96];

    const int tid = threadIdx.x, w = tid >> 5, l = tid & 31;
    const int g = l >> 2, t = l & 3;
    const int b = blockIdx.z;
    const int m0 = blockIdx.x * 96;
    const int slice = blockIdx.y;
    const int nbase = slice * 512;
    const int bN = b * N_;
    const float kmax = g_kmaxf;

    const int mloc = l + 32 * (w % 3);
    const int sgrp = w / 3;
    const int mglob = m0 + mloc;
    const bool mval = mglob < M_;
    const int vg = w >> 1;
    const int ve = l + 32 * (w & 1);

    const int e_off = (w & 1) * 32;
    const int m_off = (w >> 1) * 32;

    if (tid < 96) kss[tid] = 0.f;

    float acc[2][4][4];
#pragma unroll
    for (int mi = 0; mi < 2; mi++)
#pragma unroll
        for (int ni = 0; ni < 4; ni++)
#pragma unroll
            for (int j = 0; j < 4; j++) acc[mi][ni][j] = 0.f;
    float kslocal = 0.f;

    float pd0[4], pd1[4], pn0[4], pn1[4], pv0[4], pv1[4];
#pragma unroll
    for (int ii = 0; ii < 4; ii++) {
        const int n = nbase + 2 * (4 * sgrp + ii);
        pd0[ii] = g_kdash[(size_t)(bN + n) * MP_ + mglob];
        pd1[ii] = g_kdash[(size_t)(bN + n + 1) * MP_ + mglob];
        pn0[ii] = g_knorm[bN + n];
        pn1[ii] = g_knorm[bN + n + 1];
    }
    if (w < 4) {
#pragma unroll
        for (int ii = 0; ii < 4; ii++) {
            const int n = nbase + 2 * (4 * vg + ii);
            pv0[ii] = v[(size_t)(bN + n) * 64 + ve];
            pv1[ii] = v[(size_t)(bN + n + 1) * 64 + ve];
        }
    }

    for (int ck = 0; ck < 32; ck++) {
        const int cur = ck & 1;
        uint32_t* vah = VAh[cur]; uint32_t* val_ = VAl[cur];
        uint32_t* kbh = KBh[cur]; uint32_t* kbl = KBl[cur];

        float d0c[4], d1c[4], n0c[4], n1c[4], v0c[4], v1c[4];
#pragma unroll
        for (int ii = 0; ii < 4; ii++) {
            d0c[ii] = pd0[ii]; d1c[ii] = pd1[ii];
            n0c[ii] = pn0[ii]; n1c[ii] = pn1[ii];
            v0c[ii] = pv0[ii]; v1c[ii] = pv1[ii];
        }
        if (ck < 31) {
            const int nn = nbase + 16 * (ck + 1);
#pragma unroll
            for (int ii = 0; ii < 4; ii++) {
                const int n = nn + 2 * (4 * sgrp + ii);
                pd0[ii] = g_kdash[(size_t)(bN + n) * MP_ + mglob];
                pd1[ii] = g_kdash[(size_t)(bN + n + 1) * MP_ + mglob];
                pn0[ii] = g_knorm[bN + n];
                pn1[ii] = g_knorm[bN + n + 1];
            }
            if (w < 4) {
#pragma unroll
                for (int ii = 0; ii < 4; ii++) {
                    const int n = nn + 2 * (4 * vg + ii);
                    pv0[ii] = v[(size_t)(bN + n) * 64 + ve];
                    pv1[ii] = v[(size_t)(bN + n + 1) * 64 + ve];
                }
            }
        }
#pragma unroll
        for (int ii = 0; ii < 4; ii++) {
            const int i = 4 * sgrp + ii;
            float kp0 = mval ? RATIO_ * (__expf(d0c[ii] - n0c[ii] - kmax) + EPS_) : 0.f;
            float kp1 = mval ? RATIO_ * (__expf(d1c[ii] - n1c[ii] - kmax) + EPS_) : 0.f;
            kslocal += kp0 + kp1;
            uint32_t h, lo;
            split_pack(kp0, kp1, h, lo);
            kbh[mloc * 12 + i] = h; kbl[mloc * 12 + i] = lo;
        }
        if (w < 4) {
#pragma unroll
            for (int ii = 0; ii < 4; ii++) {
                const int i = 4 * vg + ii;
                uint32_t h, lo;
                split_pack(v0c[ii], v1c[ii], h, lo);
                vah[ve * 12 + i] = h; val_[ve * 12 + i] = lo;
            }
        }
        __syncthreads();
        uint32_t ah[2][4], al[2][4];
#pragma unroll
        for (int mi = 0; mi < 2; mi++) {
            const int eR = e_off + 16 * mi;
            ah[mi][0] = vah[(eR + g) * 12 + t];
            ah[mi][1] = vah[(eR + 8 + g) * 12 + t];
            ah[mi][2] = vah[(eR + g) * 12 + t + 4];
            ah[mi][3] = vah[(eR + 8 + g) * 12 + t + 4];
            al[mi][0] = val_[(eR + g) * 12 + t];
            al[mi][1] = val_[(eR + 8 + g) * 12 + t];
            al[mi][2] = val_[(eR + g) * 12 + t + 4];
            al[mi][3] = val_[(eR + 8 + g) * 12 + t + 4];
        }
#pragma unroll
        for (int ni = 0; ni < 4; ni++) {
            const int cw = (m_off + 8 * ni + g) * 12;
            uint32_t bh0 = kbh[cw + t], bh1 = kbh[cw + t + 4];
            uint32_t bl0 = kbl[cw + t], bl1 = kbl[cw + t + 4];
#pragma unroll
            for (int mi = 0; mi < 2; mi++) {
                mma_bf16(acc[mi][ni], ah[mi], bh0, bh1);
                mma_bf16(acc[mi][ni], ah[mi], bl0, bl1);
                mma_bf16(acc[mi][ni], al[mi], bh0, bh1);
            }
        }
    }

    // ksum partial: shared accumulate then plain store
    atomicAdd(&kss[mloc], kslocal);
    __syncthreads();
    if (tid < 96) g_ksumP[((size_t)(slice * B_ + b)) * MP_ + m0 + tid] = kss[tid];

    // ctx partial: plain stores (every slot covered exactly once)
    float* base = g_ctxP + slice * CTXS_;
#pragma unroll
    for (int mi = 0; mi < 2; mi++) {
        const int e0 = e_off + 16 * mi + g;
#pragma unroll
        for (int ni = 0; ni < 4; ni++) {
            const int mc = m0 + m_off + 8 * ni + 2 * t;
            *(float2*)&base[((size_t)(b * 64 + e0)) * MP_ + mc] =
                make_float2(acc[mi][ni][0], acc[mi][ni][1]);
            *(float2*)&base[((size_t)(b * 64 + e0 + 8)) * MP_ + mc] =
                make_float2(acc[mi][ni][2], acc[mi][ni][3]);
        }
    }
}

// ---------------- K3: out = (qp @ ctx^T) * dinv (double-buffered) --------------
#define K3_QPH 0          // 2 x 10240
#define K3_QPL 20480      // 2 x 10240
#define K3_CBH 40960      // 2 x 5120
#define K3_CBL 51200      // 2 x 5120
#define K3_DI  61440
#define K3_KS  61952
#define K3_SM  63232

__global__ __launch_bounds__(256)
void k3_out(float* __restrict__ out) {
    extern __shared__ char sm3[];
    float* OB   = (float*)sm3;                 // union with buffers (post-loop)
    float* dinv = (float*)(sm3 + K3_DI);
    float* ksum_s = (float*)(sm3 + K3_KS);

    const int tid = threadIdx.x, w = tid >> 5, l = tid & 31;
    const int g = l >> 2, t = l & 3;
    const int b = blockIdx.y;
    const int r0 = blockIdx.x * 128;
    const int bN = b * N_;

    const int sr = tid >> 1, shalf = tid & 1;
    const int se = tid >> 2, sq4 = tid & 3;

    const int gr = bN + r0 + sr;
    const float qn = g_qnorm[gr];
    const float qm = fmaxf(g_qmax2[gr], g_qmax2[NROWS_ + gr]);

    const int r_off = (w & 3) * 32;
    const int e_off = (w >> 2) * 32;

    // ksum = sum of 4 slice partials, staged once
    for (int i = tid; i < MP_; i += 256) {
        float s = 0.f;
#pragma unroll
        for (int s4 = 0; s4 < 4; s4++)
            s += g_ksumP[((size_t)(s4 * B_ + b)) * MP_ + i];
        ksum_s[i] = s;
    }
    __syncthreads();

    float acc[2][4][4];
#pragma unroll
    for (int mi = 0; mi < 2; mi++)
#pragma unroll
        for (int ni = 0; ni < 4; ni++)
#pragma unroll
            for (int j = 0; j < 4; j++) acc[mi][ni][j] = 0.f;
    float Dpart = 0.f;

    const float* qsrc = g_qdash + (size_t)gr * MP_ + 16 * shalf;
    const float* csrc = g_ctxP + ((size_t)(b * 64 + se)) * MP_ + 8 * sq4;

    float4 pq[4], pc[2];
#pragma unroll
    for (int j = 0; j < 4; j++) pq[j] = *(const float4*)(qsrc + 4 * j);
#pragma unroll
    for (int j = 0; j < 2; j++) {
        float4 a0 = *(const float4*)(csrc + 4 * j);
        float4 a1 = *(const float4*)(csrc + CTXS_ + 4 * j);
        float4 a2 = *(const float4*)(csrc + 2 * CTXS_ + 4 * j);
        float4 a3 = *(const float4*)(csrc + 3 * CTXS_ + 4 * j);
        pc[j] = make_float4(a0.x + a1.x + a2.x + a3.x, a0.y + a1.y + a2.y + a3.y,
                            a0.z + a1.z + a2.z + a3.z, a0.w + a1.w + a2.w + a3.w);
    }

    for (int ck = 0; ck < 9; ck++) {
        const int cur = ck & 1;
        uint32_t* QPh = (uint32_t*)(sm3 + K3_QPH) + cur * 2560;
        uint32_t* QPl = (uint32_t*)(sm3 + K3_QPL) + cur * 2560;
        uint32_t* CBh = (uint32_t*)(sm3 + K3_CBH) + cur * 1280;
        uint32_t* CBl = (uint32_t*)(sm3 + K3_CBL) + cur * 1280;

        const int m0 = 32 * ck;
        float4 d[4], cc[2];
#pragma unroll
        for (int j = 0; j < 4; j++) d[j] = pq[j];
#pragma unroll
        for (int j = 0; j < 2; j++) cc[j] = pc[j];
        if (ck < 8) {
#pragma unroll
            for (int j = 0; j < 4; j++)
                pq[j] = *(const float4*)(qsrc + 32 * (ck + 1) + 4 * j);
#pragma unroll
            for (int j = 0; j < 2; j++) {
                const float* p = csrc + 32 * (ck + 1) + 4 * j;
                float4 a0 = *(const float4*)p;
                float4 a1 = *(const float4*)(p + CTXS_);
                float4 a2 = *(const float4*)(p + 2 * CTXS_);
                float4 a3 = *(const float4*)(p + 3 * CTXS_);
                pc[j] = make_float4(a0.x + a1.x + a2.x + a3.x, a0.y + a1.y + a2.y + a3.y,
                                    a0.z + a1.z + a2.z + a3.z, a0.w + a1.w + a2.w + a3.w);
            }
        }
        {
#pragma unroll
            for (int j = 0; j < 4; j++) {
                const int mb = m0 + 16 * shalf + 4 * j;
                float4 ks4 = *(float4*)&ksum_s[mb];
                float q0 = (mb < M_) ? RATIO_ * (__expf(d[j].x - qn - qm) + EPS_) : 0.f;
                float q1 = (mb + 1 < M_) ? RATIO_ * (__expf(d[j].y - qn - qm) + EPS_) : 0.f;
                float q2 = (mb + 2 < M_) ? RATIO_ * (__expf(d[j].z - qn - qm) + EPS_) : 0.f;
                float q3 = (mb + 3 < M_) ? RATIO_ * (__expf(d[j].w - qn - qm) + EPS_) : 0.f;
                Dpart += q0 * ks4.x + q1 * ks4.y + q2 * ks4.z + q3 * ks4.w;
                uint32_t h0, l0, h1, l1;
                split_pack(q0, q1, h0, l0);
                split_pack(q2, q3, h1, l1);
                const int i = 8 * shalf + 2 * j;
                QPh[sr * 20 + i] = h0; QPh[sr * 20 + i + 1] = h1;
                QPl[sr * 20 + i] = l0; QPl[sr * 20 + i + 1] = l1;
            }
        }
#pragma unroll
        for (int j = 0; j < 2; j++) {
            uint32_t h0, l0, h1, l1;
            split_pack(cc[j].x, cc[j].y, h0, l0);
            split_pack(cc[j].z, cc[j].w, h1, l1);
            const int i = 4 * sq4 + 2 * j;
            CBh[se * 20 + i] = h0; CBh[se * 20 + i + 1] = h1;
            CBl[se * 20 + i] = l0; CBl[se * 20 + i + 1] = l1;
        }
        __syncthreads();
#pragma unroll
        for (int kk = 0; kk < 2; kk++) {
            const int c = 8 * kk + t;
            uint32_t ah[2][4], al[2][4];
#pragma unroll
            for (int mi = 0; mi < 2; mi++) {
                const int rA = r_off + 16 * mi;
                ah[mi][0] = QPh[(rA + g) * 20 + c];
                ah[mi][1] = QPh[(rA + 8 + g) * 20 + c];
                ah[mi][2] = QPh[(rA + g) * 20 + c + 4];
                ah[mi][3] = QPh[(rA + 8 + g) * 20 + c + 4];
                al[mi][0] = QPl[(rA + g) * 20 + c];
                al[mi][1] = QPl[(rA + 8 + g) * 20 + c];
                al[mi][2] = QPl[(rA + g) * 20 + c + 4];
                al[mi][3] = QPl[(rA + 8 + g) * 20 + c + 4];
            }
#pragma unroll
            for (int ni = 0; ni < 4; ni++) {
                const int cw = (e_off + 8 * ni + g) * 20;
                uint32_t bh0 = CBh[cw + c], bh1 = CBh[cw + c + 4];
                uint32_t bl0 = CBl[cw + c], bl1 = CBl[cw + c + 4];
#pragma unroll
                for (int mi = 0; mi < 2; mi++) {
                    mma_bf16(acc[mi][ni], ah[mi], bh0, bh1);
                    mma_bf16(acc[mi][ni], ah[mi], bl0, bl1);
                    mma_bf16(acc[mi][ni], al[mi], bh0, bh1);
                }
            }
        }
    }

    Dpart += __shfl_xor_sync(0xffffffffu, Dpart, 1);
    if ((tid & 1) == 0) dinv[sr] = 1.f / Dpart;
    __syncthreads();

#pragma unroll
    for (int mi = 0; mi < 2; mi++) {
        const int rl0 = r_off + 16 * mi + g;
        const float di0 = dinv[rl0], di1 = dinv[rl0 + 8];
#pragma unroll
        for (int ni = 0; ni < 4; ni++) {
            const int col = e_off + 8 * ni + 2 * t;
            *(float2*)&OB[rl0 * 76 + col] =
                make_float2(acc[mi][ni][0] * di0, acc[mi][ni][1] * di0);
            *(float2*)&OB[(rl0 + 8) * 76 + col] =
                make_float2(acc[mi][ni][2] * di1, acc[mi][ni][3] * di1);
        }
    }
    __syncthreads();
    for (int i = tid; i < 2048; i += 256) {
        const int r = i >> 4, c4 = i & 15;
        *(float4*)&out[((size_t)(bN + r0 + r)) * 64 + 4 * c4] =
            *(float4*)&OB[r * 76 + 4 * c4];
    }
}

// ---------------- launcher ----------------
extern "C" void kernel_launch(void* const* d_in, const int* in_sizes, int n_in,
                              void* d_out, int out_size) {
    const float* q    = (const float*)d_in[0];
    const float* k    = (const float*)d_in[1];
    const float* v    = (const float*)d_in[2];
    const float* proj = (const float*)d_in[3];
    float* out = (float*)d_out;

    static int configured = 0;
    if (!configured) {
        cudaFuncSetAttribute(k1_proj, cudaFuncAttributeMaxDynamicSharedMemorySize, K1_SM);
        cudaFuncSetAttribute(k3_out, cudaFuncAttributeMaxDynamicSharedMemorySize, K3_SM);
        configured = 1;
    }

    k1_proj<<<dim3(1024, 2, 2), 256, K1_SM>>>(q, k, proj);
    k1c_kmax<<<1, 256>>>();
    k2_ctx<<<dim3(3, 4, 64), 192>>>(v);
    k3_out<<<dim3(16, 64), 256, K3_SM>>>(out);
}